// round 14
// baseline (speedup 1.0000x reference)
#include <cuda_runtime.h>
#include <math.h>
#include <stdint.h>

#define BB   64
#define SS   2048
#define EH   512
#define AH   512

#define SPLITS 64
#define SCH    (SS / SPLITS)    // 32

// scratch (no allocations allowed)
__device__ float g_dec_proj[BB * AH];
__device__ float g_score[BB * SS];
__device__ float g_ctx_part[SPLITS * BB * EH];

// ---------------------------------------------------------------------------
__device__ __forceinline__ uint32_t f2tf32(float x) {
    uint32_t r;
    asm("cvt.rna.tf32.f32 %0, %1;" : "=r"(r) : "f"(x));
    return r;
}
__device__ __forceinline__ float fast_tanh(float x) {
    float y; asm("tanh.approx.f32 %0, %1;" : "=f"(y) : "f"(x)); return y;
}
__device__ __forceinline__ void mma_tf32(float* c, const uint32_t* a, const uint32_t* b) {
    asm volatile(
        "mma.sync.aligned.m16n8k8.row.col.f32.tf32.tf32.f32 "
        "{%0,%1,%2,%3}, {%4,%5,%6,%7}, {%8,%9}, {%0,%1,%2,%3};\n"
        : "+f"(c[0]), "+f"(c[1]), "+f"(c[2]), "+f"(c[3])
        : "r"(a[0]), "r"(a[1]), "r"(a[2]), "r"(a[3]),
          "r"(b[0]), "r"(b[1]));
}

// ---------------------------------------------------------------------------
// K1: dec_proj[b,a] = sum_d dec_hidden[b,d] * W_dec[a,d]   grid (BB, 4)
// ---------------------------------------------------------------------------
__global__ void dec_proj_kernel(const float* __restrict__ dec_hidden,
                                const float* __restrict__ W_dec) {
    int b  = blockIdx.x;
    int ab = blockIdx.y * 128;
    __shared__ float sh[EH];
    for (int i = threadIdx.x; i < EH; i += blockDim.x)
        sh[i] = dec_hidden[b * EH + i];
    __syncthreads();

    int warp = threadIdx.x >> 5;
    int lane = threadIdx.x & 31;
    for (int a = warp; a < 128; a += 8) {
        const float* wr = W_dec + (size_t)(ab + a) * EH;
        float acc = 0.f;
        #pragma unroll 4
        for (int d = lane; d < EH; d += 32)
            acc += sh[d] * wr[d];
        #pragma unroll
        for (int o = 16; o > 0; o >>= 1)
            acc += __shfl_xor_sync(0xffffffffu, acc, o);
        if (lane == 0) g_dec_proj[b * AH + ab + a] = acc;
    }
}

// ---------------------------------------------------------------------------
// K2: fused score kernel (tf32 mma.sync m16n8k8), frag-major smem layout.
//     4-stage ring buffer (1 barrier / 2 chunks), cross-pass pipelined,
//     pass-parity double-buffered sv/sdec/red (no end-of-pass barrier).
//   score[b,s] = sum_a tanh(enc_proj[b,s,a] + dec_proj[b,a]) * v[a]
// ---------------------------------------------------------------------------
#define KT     32
#define NKCH   16          // chunks per a-pass; 64 global chunks
#define AW_PAD 1028
#define BW_PAD 1026
#define AWORDS (4 * AW_PAD)
#define BWORDS (4 * BW_PAD)
#define STWORDS (AWORDS + BWORDS)       // 8216 words per stage
#define OFF_ST0  0
#define OFF_ST1  (1 * STWORDS)
#define OFF_ST2  (2 * STWORDS)
#define OFF_ST3  (3 * STWORDS)
#define OFF_SV   (4 * STWORDS)          // 2 x 128
#define OFF_SDEC (OFF_SV + 256)         // 2 x 128
#define OFF_RED  (OFF_SDEC + 256)       // 2 x 512
#define SMEM_WORDS (OFF_RED + 1024)
#define SMEM_BYTES (SMEM_WORDS * 4)     // 137600

// load regs for GLOBAL chunk gi (pass = gi>>4, k0 = (gi&15)*KT)
__device__ __forceinline__ void load_regs_g(float4* ra, float4* rb,
                                            const float* __restrict__ encb,
                                            const float* __restrict__ Wenc,
                                            int gi, int tid) {
    const int k0 = (gi & 15) * KT;
    const float* wbp = Wenc + (size_t)(gi >> 4) * 128 * EH;
    #pragma unroll
    for (int j = 0; j < 4; j++) {
        int i = tid + j * 256;
        int m = i >> 3, k4 = i & 7;
        ra[j] = *(const float4*)&encb[(size_t)m * EH + k0 + k4 * 4];
        rb[j] = *(const float4*)&wbp [(size_t)m * EH + k0 + k4 * 4];
    }
}

// stage pointer: A tile at stage base, B tile at stage base + AWORDS
__device__ __forceinline__ void store_tiles(uint32_t* __restrict__ St,
                                            const float4* ra, const float4* rb,
                                            int tid) {
    uint32_t* Ab = St;
    uint32_t* Bb = St + AWORDS;
    #pragma unroll
    for (int j = 0; j < 4; j++) {
        int i = tid + j * 256;
        int m = i >> 3, k4 = i & 7;
        int kb = k4 >> 1, khigh = k4 & 1;
        {
            int mb = m >> 4, gg = m & 7, rh = (m >> 3) & 1;
            int base = kb * AW_PAD + mb * 128 + khigh * 2 + rh;
            const float* f = &ra[j].x;
            #pragma unroll
            for (int c = 0; c < 4; c++)
                Ab[base + (gg * 4 + c) * 4] = f2tf32(f[c]);
        }
        {
            int nb = m >> 3, gg = m & 7;
            int base = kb * BW_PAD + nb * 64 + khigh;
            const float* f = &rb[j].x;
            #pragma unroll
            for (int c = 0; c < 4; c++)
                Bb[base + (gg * 4 + c) * 2] = f2tf32(f[c]);
        }
    }
}

__device__ __forceinline__ void mma_block(const uint32_t* __restrict__ St,
                                          float acc[4][4][4], int wid, int lane) {
    const uint32_t* As = St;
    const uint32_t* Bs = St + AWORDS;
    #pragma unroll
    for (int kb = 0; kb < 4; kb++) {
        uint4 af[4];
        #pragma unroll
        for (int mf = 0; mf < 4; mf++) {
            int mb = (wid & 1) * 4 + mf;
            af[mf] = *(const uint4*)&As[kb * AW_PAD + mb * 128 + lane * 4];
        }
        uint2 bf[4];
        #pragma unroll
        for (int nf = 0; nf < 4; nf++) {
            int nb = (wid >> 1) * 4 + nf;
            bf[nf] = *(const uint2*)&Bs[kb * BW_PAD + nb * 64 + lane * 2];
        }
        #pragma unroll
        for (int mf = 0; mf < 4; mf++)
            #pragma unroll
            for (int nf = 0; nf < 4; nf++)
                mma_tf32(acc[mf][nf], (const uint32_t*)&af[mf],
                         (const uint32_t*)&bf[nf]);
    }
}

__global__ void __launch_bounds__(256, 1) score_kernel(
        const float* __restrict__ enc,
        const float* __restrict__ Wenc,
        const float* __restrict__ v) {
    extern __shared__ uint32_t dsm[];
    const int b  = blockIdx.y;
    const int s0 = blockIdx.x * 128;
    const int tid = threadIdx.x;
    const int wid = tid >> 5;
    const int lane = tid & 31;
    const int g = lane >> 2;
    const int t = lane & 3;
    const int warp_m = (wid & 1) * 64;
    const int warp_n = (wid >> 1) * 32;
    const int wn_idx = wid >> 1;

    uint32_t* const T0 = dsm + OFF_ST0;
    uint32_t* const T1 = dsm + OFF_ST1;
    uint32_t* const T2 = dsm + OFF_ST2;
    uint32_t* const T3 = dsm + OFF_ST3;
    float* sv   = (float*)(dsm + OFF_SV);     // [2][128]
    float* sdec = (float*)(dsm + OFF_SDEC);   // [2][128]
    float* red  = (float*)(dsm + OFF_RED);    // [2][512]

    const float* encb = enc + ((size_t)b * SS + s0) * EH;

    float srow = 0.f;

    // ---- prologue: chunks 0,1 -> T0,T1 (overlapped LDG rounds) ----
    float4 ra[4], rb[4], ra2[4], rb2[4];
    load_regs_g(ra,  rb,  encb, Wenc, 0, tid);
    load_regs_g(ra2, rb2, encb, Wenc, 1, tid);
    store_tiles(T0, ra,  rb,  tid);
    store_tiles(T1, ra2, rb2, tid);
    __syncthreads();

    for (int pass = 0; pass < 4; pass++) {
        const int a0 = pass * 128;
        const int par = pass & 1;
        float* svp   = sv   + par * 128;
        float* sdecp = sdec + par * 128;
        float* redp  = red  + par * 512;

        if (tid < 128) {
            svp[tid]   = v[a0 + tid];
            sdecp[tid] = g_dec_proj[b * AH + a0 + tid];
        }

        float acc[4][4][4];
        #pragma unroll
        for (int mf = 0; mf < 4; mf++)
            #pragma unroll
            for (int nf = 0; nf < 4; nf++)
                #pragma unroll
                for (int cc = 0; cc < 4; cc++) acc[mf][nf][cc] = 0.f;

        // ---- 4-chunk super-regions, one barrier per 2 chunks ----
        for (int ci = 0; ci < NKCH; ci += 4) {
            const int gi = pass * NKCH + ci;

            // region A: chunks gi (T0), gi+1 (T1); store gi+2->T2, gi+3->T3
            load_regs_g(ra, rb, encb, Wenc, gi + 2, tid);   // gi+2 <= 62
            mma_block(T0, acc, wid, lane);
            store_tiles(T2, ra, rb, tid);
            load_regs_g(ra, rb, encb, Wenc, gi + 3, tid);   // gi+3 <= 63
            mma_block(T1, acc, wid, lane);
            store_tiles(T3, ra, rb, tid);
            __syncthreads();

            // region B: chunks gi+2 (T2), gi+3 (T3); store gi+4->T0, gi+5->T1
            const bool p4 = (gi + 4 < 64);
            const bool p5 = (gi + 5 < 64);
            if (p4) load_regs_g(ra, rb, encb, Wenc, gi + 4, tid);
            mma_block(T2, acc, wid, lane);
            if (p4) store_tiles(T0, ra, rb, tid);
            if (p5) load_regs_g(ra, rb, encb, Wenc, gi + 5, tid);
            mma_block(T3, acc, wid, lane);
            if (p5) store_tiles(T1, ra, rb, tid);
            __syncthreads();
        }

        // ---- epilogue: tanh(acc + dec) * v, reduce over the 128 a-cols ----
        float rowsum[4][2];
        #pragma unroll
        for (int mf = 0; mf < 4; mf++) { rowsum[mf][0] = 0.f; rowsum[mf][1] = 0.f; }

        #pragma unroll
        for (int mf = 0; mf < 4; mf++) {
            #pragma unroll
            for (int nf = 0; nf < 4; nf++) {
                int nbase = warp_n + nf * 8 + t * 2;
                #pragma unroll
                for (int cc = 0; cc < 4; cc++) {
                    int n = nbase + (cc & 1);
                    float x = acc[mf][nf][cc] + sdecp[n];
                    rowsum[mf][cc >> 1] += fast_tanh(x) * svp[n];
                }
            }
        }
        #pragma unroll
        for (int mf = 0; mf < 4; mf++) {
            #pragma unroll
            for (int o = 0; o < 2; o++) {
                rowsum[mf][o] += __shfl_xor_sync(0xffffffffu, rowsum[mf][o], 1);
                rowsum[mf][o] += __shfl_xor_sync(0xffffffffu, rowsum[mf][o], 2);
            }
        }
        if (t == 0) {
            #pragma unroll
            for (int mf = 0; mf < 4; mf++) {
                redp[(warp_m + mf * 16 + g)     * 4 + wn_idx] = rowsum[mf][0];
                redp[(warp_m + mf * 16 + g + 8) * 4 + wn_idx] = rowsum[mf][1];
            }
        }
        __syncthreads();
        if (tid < 128) {
            float4 rr = *(const float4*)&redp[tid * 4];
            srow += (rr.x + rr.y) + (rr.z + rr.w);
        }
        // no end-of-pass barrier: next pass writes only the opposite-parity
        // sv/sdec/red buffers; T-buffer ordering is carried by K-loop barriers.
    }

    if (tid < 128)
        g_score[b * SS + s0 + tid] = srow;
}

// ---------------------------------------------------------------------------
// K3 (fused): softmax (recomputed per block, deterministic) + partial context.
// ---------------------------------------------------------------------------
__global__ void __launch_bounds__(128) context_partial_kernel(
        const float* __restrict__ enc,
        float* __restrict__ out_w) {
    const int b   = blockIdx.x;
    const int sp  = blockIdx.y;
    const int tid = threadIdx.x;
    const int lane = tid & 31;
    const int warp = tid >> 5;

    __shared__ float sredm[4];
    __shared__ float sreds[4];
    __shared__ float wsm[SCH];

    const float* srow = g_score + b * SS;

    float vals[16];
    float vmax = -1e30f;
    #pragma unroll
    for (int i = 0; i < 4; i++) {
        float4 v4 = *(const float4*)&srow[tid * 16 + i * 4];
        vals[i * 4 + 0] = v4.x; vals[i * 4 + 1] = v4.y;
        vals[i * 4 + 2] = v4.z; vals[i * 4 + 3] = v4.w;
    }
    #pragma unroll
    for (int i = 0; i < 16; i++) vmax = fmaxf(vmax, vals[i]);
    #pragma unroll
    for (int o = 16; o > 0; o >>= 1)
        vmax = fmaxf(vmax, __shfl_xor_sync(0xffffffffu, vmax, o));
    if (lane == 0) sredm[warp] = vmax;
    __syncthreads();
    float bmax = fmaxf(fmaxf(sredm[0], sredm[1]), fmaxf(sredm[2], sredm[3]));

    float vsum = 0.f;
    #pragma unroll
    for (int i = 0; i < 16; i++) {
        vals[i] = expf(vals[i] - bmax);
        vsum += vals[i];
    }
    #pragma unroll
    for (int o = 16; o > 0; o >>= 1)
        vsum += __shfl_xor_sync(0xffffffffu, vsum, o);
    if (lane == 0) sreds[warp] = vsum;
    __syncthreads();
    float bsum = ((sreds[0] + sreds[1]) + (sreds[2] + sreds[3]));
    float inv = __frcp_rn(bsum);

    if (sp == 0) {
        #pragma unroll
        for (int i = 0; i < 16; i++)
            out_w[b * SS + tid * 16 + i] = vals[i] * inv;
    }

    if (tid < SCH)
        wsm[tid] = expf(srow[sp * SCH + tid] - bmax) * inv;
    __syncthreads();

    const int e4 = tid << 2;
    const float* encb = enc + ((size_t)b * SS + (size_t)sp * SCH) * EH + e4;

    float4 acc = make_float4(0.f, 0.f, 0.f, 0.f);
    #pragma unroll 8
    for (int s = 0; s < SCH; s++) {
        float ws = wsm[s];
        float4 ev = *(const float4*)(encb + (size_t)s * EH);
        acc.x += ws * ev.x;
        acc.y += ws * ev.y;
        acc.z += ws * ev.z;
        acc.w += ws * ev.w;
    }
    *(float4*)&g_ctx_part[((size_t)sp * BB + b) * EH + e4] = acc;
}

// ---------------------------------------------------------------------------
// K4: deterministic reduce, 4-way split-parallel (grid 512 x 256).
//   group t sums splits [16t, 16t+16); groups combined in fixed tree order.
// ---------------------------------------------------------------------------
__global__ void __launch_bounds__(256) context_reduce_kernel(float* __restrict__ ctx) {
    __shared__ float part[4][64];
    const int t  = threadIdx.x >> 6;          // split-group 0..3
    const int el = threadIdx.x & 63;
    const int i  = blockIdx.x * 64 + el;      // element 0..BB*EH-1

    float s = 0.f;
    #pragma unroll
    for (int j = 0; j < 16; j++)
        s += g_ctx_part[(size_t)(t * 16 + j) * BB * EH + i];
    part[t][el] = s;
    __syncthreads();
    if (t == 0)
        ctx[i] = ((part[0][el] + part[1][el]) + (part[2][el] + part[3][el]));
}

// ---------------------------------------------------------------------------
extern "C" void kernel_launch(void* const* d_in, const int* in_sizes, int n_in,
                              void* d_out, int out_size) {
    const float* enc   = (const float*)d_in[0];  // [B,S,EH]
    const float* dec   = (const float*)d_in[1];  // [B,EH]
    const float* W_enc = (const float*)d_in[2];  // [AH,EH]
    const float* W_dec = (const float*)d_in[3];  // [AH,EH]
    const float* v     = (const float*)d_in[4];  // [1,AH]

    float* out = (float*)d_out;
    float* out_ctx = out;                 // [B, EH]
    float* out_w   = out + BB * EH;       // [B, S]

    static int smem_set = 0;
    if (!smem_set) {
        cudaFuncSetAttribute(score_kernel,
                             cudaFuncAttributeMaxDynamicSharedMemorySize,
                             SMEM_BYTES);
        smem_set = 1;
    }

    dim3 g1(BB, 4);
    dec_proj_kernel<<<g1, 256>>>(dec, W_dec);

    dim3 g2(SS / 128, BB);
    score_kernel<<<g2, 256, SMEM_BYTES>>>(enc, W_enc, v);

    dim3 g3(BB, SPLITS);
    context_partial_kernel<<<g3, 128>>>(enc, out_w);

    context_reduce_kernel<<<(BB * EH) / 64, 256>>>(out_ctx);
}

// round 15
// speedup vs baseline: 1.0096x; 1.0096x over previous
#include <cuda_runtime.h>
#include <math.h>
#include <stdint.h>

#define BB   64
#define SS   2048
#define EH   512
#define AH   512

#define SPLITS 64
#define SCH    (SS / SPLITS)    // 32

// scratch (no allocations allowed)
__device__ float g_dec_proj[BB * AH];
__device__ float g_score[BB * SS];
__device__ float g_ctx_part[SPLITS * BB * EH];

// ---------------------------------------------------------------------------
__device__ __forceinline__ uint32_t f2tf32(float x) {
    uint32_t r;
    asm("cvt.rna.tf32.f32 %0, %1;" : "=r"(r) : "f"(x));
    return r;
}
__device__ __forceinline__ float fast_tanh(float x) {
    float y; asm("tanh.approx.f32 %0, %1;" : "=f"(y) : "f"(x)); return y;
}
__device__ __forceinline__ void mma_tf32(float* c, const uint32_t* a, const uint32_t* b) {
    asm volatile(
        "mma.sync.aligned.m16n8k8.row.col.f32.tf32.tf32.f32 "
        "{%0,%1,%2,%3}, {%4,%5,%6,%7}, {%8,%9}, {%0,%1,%2,%3};\n"
        : "+f"(c[0]), "+f"(c[1]), "+f"(c[2]), "+f"(c[3])
        : "r"(a[0]), "r"(a[1]), "r"(a[2]), "r"(a[3]),
          "r"(b[0]), "r"(b[1]));
}

// ---------------------------------------------------------------------------
// K1: dec_proj[b,a] = sum_d dec_hidden[b,d] * W_dec[a,d]   grid (BB, 4)
// ---------------------------------------------------------------------------
__global__ void dec_proj_kernel(const float* __restrict__ dec_hidden,
                                const float* __restrict__ W_dec) {
    int b  = blockIdx.x;
    int ab = blockIdx.y * 128;
    __shared__ float sh[EH];
    for (int i = threadIdx.x; i < EH; i += blockDim.x)
        sh[i] = dec_hidden[b * EH + i];
    __syncthreads();

    int warp = threadIdx.x >> 5;
    int lane = threadIdx.x & 31;
    for (int a = warp; a < 128; a += 8) {
        const float* wr = W_dec + (size_t)(ab + a) * EH;
        float acc = 0.f;
        #pragma unroll 4
        for (int d = lane; d < EH; d += 32)
            acc += sh[d] * wr[d];
        #pragma unroll
        for (int o = 16; o > 0; o >>= 1)
            acc += __shfl_xor_sync(0xffffffffu, acc, o);
        if (lane == 0) g_dec_proj[b * AH + ab + a] = acc;
    }
}

// ---------------------------------------------------------------------------
// K2: fused score kernel (tf32 mma.sync m16n8k8), frag-major smem layout.
//     4-stage ring buffer, ONE barrier per TWO chunks, cross-pass pipelined.
//     (exact R13 structure — verified 580.0us configuration)
//   score[b,s] = sum_a tanh(enc_proj[b,s,a] + dec_proj[b,a]) * v[a]
// ---------------------------------------------------------------------------
#define KT     32
#define NKCH   16          // chunks per a-pass; 64 global chunks
#define AW_PAD 1028
#define BW_PAD 1026
#define AWORDS (4 * AW_PAD)
#define BWORDS (4 * BW_PAD)
#define STWORDS (AWORDS + BWORDS)       // 8216 words per stage
#define OFF_ST0  0
#define OFF_ST1  (1 * STWORDS)
#define OFF_ST2  (2 * STWORDS)
#define OFF_ST3  (3 * STWORDS)
#define OFF_SV   (4 * STWORDS)
#define OFF_SDEC (OFF_SV + 128)
#define OFF_RED  (OFF_SDEC + 128)
#define SMEM_WORDS (OFF_RED + 512)
#define SMEM_BYTES (SMEM_WORDS * 4)     // 134528

// load regs for GLOBAL chunk gi (pass = gi>>4, k0 = (gi&15)*KT)
__device__ __forceinline__ void load_regs_g(float4* ra, float4* rb,
                                            const float* __restrict__ encb,
                                            const float* __restrict__ Wenc,
                                            int gi, int tid) {
    const int k0 = (gi & 15) * KT;
    const float* wbp = Wenc + (size_t)(gi >> 4) * 128 * EH;
    #pragma unroll
    for (int j = 0; j < 4; j++) {
        int i = tid + j * 256;
        int m = i >> 3, k4 = i & 7;
        ra[j] = *(const float4*)&encb[(size_t)m * EH + k0 + k4 * 4];
        rb[j] = *(const float4*)&wbp [(size_t)m * EH + k0 + k4 * 4];
    }
}

// stage pointer: A tile at stage base, B tile at stage base + AWORDS
__device__ __forceinline__ void store_tiles(uint32_t* __restrict__ St,
                                            const float4* ra, const float4* rb,
                                            int tid) {
    uint32_t* Ab = St;
    uint32_t* Bb = St + AWORDS;
    #pragma unroll
    for (int j = 0; j < 4; j++) {
        int i = tid + j * 256;
        int m = i >> 3, k4 = i & 7;
        int kb = k4 >> 1, khigh = k4 & 1;
        {
            int mb = m >> 4, gg = m & 7, rh = (m >> 3) & 1;
            int base = kb * AW_PAD + mb * 128 + khigh * 2 + rh;
            const float* f = &ra[j].x;
            #pragma unroll
            for (int c = 0; c < 4; c++)
                Ab[base + (gg * 4 + c) * 4] = f2tf32(f[c]);
        }
        {
            int nb = m >> 3, gg = m & 7;
            int base = kb * BW_PAD + nb * 64 + khigh;
            const float* f = &rb[j].x;
            #pragma unroll
            for (int c = 0; c < 4; c++)
                Bb[base + (gg * 4 + c) * 2] = f2tf32(f[c]);
        }
    }
}

__device__ __forceinline__ void mma_block(const uint32_t* __restrict__ St,
                                          float acc[4][4][4], int wid, int lane) {
    const uint32_t* As = St;
    const uint32_t* Bs = St + AWORDS;
    #pragma unroll
    for (int kb = 0; kb < 4; kb++) {
        uint4 af[4];
        #pragma unroll
        for (int mf = 0; mf < 4; mf++) {
            int mb = (wid & 1) * 4 + mf;
            af[mf] = *(const uint4*)&As[kb * AW_PAD + mb * 128 + lane * 4];
        }
        uint2 bf[4];
        #pragma unroll
        for (int nf = 0; nf < 4; nf++) {
            int nb = (wid >> 1) * 4 + nf;
            bf[nf] = *(const uint2*)&Bs[kb * BW_PAD + nb * 64 + lane * 2];
        }
        #pragma unroll
        for (int mf = 0; mf < 4; mf++)
            #pragma unroll
            for (int nf = 0; nf < 4; nf++)
                mma_tf32(acc[mf][nf], (const uint32_t*)&af[mf],
                         (const uint32_t*)&bf[nf]);
    }
}

__global__ void __launch_bounds__(256, 1) score_kernel(
        const float* __restrict__ enc,
        const float* __restrict__ Wenc,
        const float* __restrict__ v) {
    extern __shared__ uint32_t dsm[];
    const int b  = blockIdx.y;
    const int s0 = blockIdx.x * 128;
    const int tid = threadIdx.x;
    const int wid = tid >> 5;
    const int lane = tid & 31;
    const int g = lane >> 2;
    const int t = lane & 3;
    const int warp_m = (wid & 1) * 64;
    const int warp_n = (wid >> 1) * 32;
    const int wn_idx = wid >> 1;

    uint32_t* const T0 = dsm + OFF_ST0;
    uint32_t* const T1 = dsm + OFF_ST1;
    uint32_t* const T2 = dsm + OFF_ST2;
    uint32_t* const T3 = dsm + OFF_ST3;
    float* sv   = (float*)(dsm + OFF_SV);
    float* sdec = (float*)(dsm + OFF_SDEC);
    float* red  = (float*)(dsm + OFF_RED);

    const float* encb = enc + ((size_t)b * SS + s0) * EH;

    float srow = 0.f;

    // ---- prologue: chunks 0,1 -> T0,T1 ----
    float4 ra[4], rb[4];
    load_regs_g(ra, rb, encb, Wenc, 0, tid);
    store_tiles(T0, ra, rb, tid);
    load_regs_g(ra, rb, encb, Wenc, 1, tid);
    store_tiles(T1, ra, rb, tid);
    __syncthreads();

    for (int pass = 0; pass < 4; pass++) {
        const int a0 = pass * 128;

        if (tid < 128) {
            sv[tid]   = v[a0 + tid];
            sdec[tid] = g_dec_proj[b * AH + a0 + tid];
        }

        float acc[4][4][4];
        #pragma unroll
        for (int mf = 0; mf < 4; mf++)
            #pragma unroll
            for (int nf = 0; nf < 4; nf++)
                #pragma unroll
                for (int cc = 0; cc < 4; cc++) acc[mf][nf][cc] = 0.f;

        // ---- 4-chunk super-regions, one barrier per 2 chunks ----
        for (int ci = 0; ci < NKCH; ci += 4) {
            const int gi = pass * NKCH + ci;

            // region A: chunks gi (T0), gi+1 (T1); store gi+2->T2, gi+3->T3
            load_regs_g(ra, rb, encb, Wenc, gi + 2, tid);   // gi+2 <= 62
            mma_block(T0, acc, wid, lane);
            store_tiles(T2, ra, rb, tid);
            load_regs_g(ra, rb, encb, Wenc, gi + 3, tid);   // gi+3 <= 63
            mma_block(T1, acc, wid, lane);
            store_tiles(T3, ra, rb, tid);
            __syncthreads();

            // region B: chunks gi+2 (T2), gi+3 (T3); store gi+4->T0, gi+5->T1
            const bool p4 = (gi + 4 < 64);
            const bool p5 = (gi + 5 < 64);
            if (p4) load_regs_g(ra, rb, encb, Wenc, gi + 4, tid);
            mma_block(T2, acc, wid, lane);
            if (p4) store_tiles(T0, ra, rb, tid);
            if (p5) load_regs_g(ra, rb, encb, Wenc, gi + 5, tid);
            mma_block(T3, acc, wid, lane);
            if (p5) store_tiles(T1, ra, rb, tid);
            __syncthreads();
        }

        // ---- epilogue: tanh(acc + dec) * v, reduce over the 128 a-cols ----
        float rowsum[4][2];
        #pragma unroll
        for (int mf = 0; mf < 4; mf++) { rowsum[mf][0] = 0.f; rowsum[mf][1] = 0.f; }

        #pragma unroll
        for (int mf = 0; mf < 4; mf++) {
            #pragma unroll
            for (int nf = 0; nf < 4; nf++) {
                int nbase = warp_n + nf * 8 + t * 2;
                #pragma unroll
                for (int cc = 0; cc < 4; cc++) {
                    int n = nbase + (cc & 1);
                    float x = acc[mf][nf][cc] + sdec[n];
                    rowsum[mf][cc >> 1] += fast_tanh(x) * sv[n];
                }
            }
        }
        #pragma unroll
        for (int mf = 0; mf < 4; mf++) {
            #pragma unroll
            for (int o = 0; o < 2; o++) {
                rowsum[mf][o] += __shfl_xor_sync(0xffffffffu, rowsum[mf][o], 1);
                rowsum[mf][o] += __shfl_xor_sync(0xffffffffu, rowsum[mf][o], 2);
            }
        }
        if (t == 0) {
            #pragma unroll
            for (int mf = 0; mf < 4; mf++) {
                red[(warp_m + mf * 16 + g)     * 4 + wn_idx] = rowsum[mf][0];
                red[(warp_m + mf * 16 + g + 8) * 4 + wn_idx] = rowsum[mf][1];
            }
        }
        __syncthreads();
        if (tid < 128) {
            float4 rr = *(const float4*)&red[tid * 4];
            srow += (rr.x + rr.y) + (rr.z + rr.w);
        }
        __syncthreads();   // protects red + sv/sdec for next pass
    }

    if (tid < 128)
        g_score[b * SS + s0 + tid] = srow;
}

// ---------------------------------------------------------------------------
// K3 (fused): softmax (recomputed per block, deterministic) + partial context.
// ---------------------------------------------------------------------------
__global__ void __launch_bounds__(128) context_partial_kernel(
        const float* __restrict__ enc,
        float* __restrict__ out_w) {
    const int b   = blockIdx.x;
    const int sp  = blockIdx.y;
    const int tid = threadIdx.x;
    const int lane = tid & 31;
    const int warp = tid >> 5;

    __shared__ float sredm[4];
    __shared__ float sreds[4];
    __shared__ float wsm[SCH];

    const float* srow = g_score + b * SS;

    float vals[16];
    float vmax = -1e30f;
    #pragma unroll
    for (int i = 0; i < 4; i++) {
        float4 v4 = *(const float4*)&srow[tid * 16 + i * 4];
        vals[i * 4 + 0] = v4.x; vals[i * 4 + 1] = v4.y;
        vals[i * 4 + 2] = v4.z; vals[i * 4 + 3] = v4.w;
    }
    #pragma unroll
    for (int i = 0; i < 16; i++) vmax = fmaxf(vmax, vals[i]);
    #pragma unroll
    for (int o = 16; o > 0; o >>= 1)
        vmax = fmaxf(vmax, __shfl_xor_sync(0xffffffffu, vmax, o));
    if (lane == 0) sredm[warp] = vmax;
    __syncthreads();
    float bmax = fmaxf(fmaxf(sredm[0], sredm[1]), fmaxf(sredm[2], sredm[3]));

    float vsum = 0.f;
    #pragma unroll
    for (int i = 0; i < 16; i++) {
        vals[i] = expf(vals[i] - bmax);
        vsum += vals[i];
    }
    #pragma unroll
    for (int o = 16; o > 0; o >>= 1)
        vsum += __shfl_xor_sync(0xffffffffu, vsum, o);
    if (lane == 0) sreds[warp] = vsum;
    __syncthreads();
    float bsum = ((sreds[0] + sreds[1]) + (sreds[2] + sreds[3]));
    float inv = __frcp_rn(bsum);

    if (sp == 0) {
        #pragma unroll
        for (int i = 0; i < 16; i++)
            out_w[b * SS + tid * 16 + i] = vals[i] * inv;
    }

    if (tid < SCH)
        wsm[tid] = expf(srow[sp * SCH + tid] - bmax) * inv;
    __syncthreads();

    const int e4 = tid << 2;
    const float* encb = enc + ((size_t)b * SS + (size_t)sp * SCH) * EH + e4;

    float4 acc = make_float4(0.f, 0.f, 0.f, 0.f);
    #pragma unroll 8
    for (int s = 0; s < SCH; s++) {
        float ws = wsm[s];
        float4 ev = *(const float4*)(encb + (size_t)s * EH);
        acc.x += ws * ev.x;
        acc.y += ws * ev.y;
        acc.z += ws * ev.z;
        acc.w += ws * ev.w;
    }
    *(float4*)&g_ctx_part[((size_t)sp * BB + b) * EH + e4] = acc;
}

// ---------------------------------------------------------------------------
// K4: deterministic reduce, 4-way split-parallel (grid 512 x 256).
// ---------------------------------------------------------------------------
__global__ void __launch_bounds__(256) context_reduce_kernel(float* __restrict__ ctx) {
    __shared__ float part[4][64];
    const int t  = threadIdx.x >> 6;          // split-group 0..3
    const int el = threadIdx.x & 63;
    const int i  = blockIdx.x * 64 + el;      // element 0..BB*EH-1

    float s = 0.f;
    #pragma unroll
    for (int j = 0; j < 16; j++)
        s += g_ctx_part[(size_t)(t * 16 + j) * BB * EH + i];
    part[t][el] = s;
    __syncthreads();
    if (t == 0)
        ctx[i] = ((part[0][el] + part[1][el]) + (part[2][el] + part[3][el]));
}

// ---------------------------------------------------------------------------
extern "C" void kernel_launch(void* const* d_in, const int* in_sizes, int n_in,
                              void* d_out, int out_size) {
    const float* enc   = (const float*)d_in[0];  // [B,S,EH]
    const float* dec   = (const float*)d_in[1];  // [B,EH]
    const float* W_enc = (const float*)d_in[2];  // [AH,EH]
    const float* W_dec = (const float*)d_in[3];  // [AH,EH]
    const float* v     = (const float*)d_in[4];  // [1,AH]

    float* out = (float*)d_out;
    float* out_ctx = out;                 // [B, EH]
    float* out_w   = out + BB * EH;       // [B, S]

    static int smem_set = 0;
    if (!smem_set) {
        cudaFuncSetAttribute(score_kernel,
                             cudaFuncAttributeMaxDynamicSharedMemorySize,
                             SMEM_BYTES);
        smem_set = 1;
    }

    dim3 g1(BB, 4);
    dec_proj_kernel<<<g1, 256>>>(dec, W_dec);

    dim3 g2(SS / 128, BB);
    score_kernel<<<g2, 256, SMEM_BYTES>>>(enc, W_enc, v);

    dim3 g3(BB, SPLITS);
    context_partial_kernel<<<g3, 128>>>(enc, out_w);

    context_reduce_kernel<<<(BB * EH) / 64, 256>>>(out_ctx);
}

// round 16
// speedup vs baseline: 1.0401x; 1.0302x over previous
#include <cuda_runtime.h>
#include <math.h>
#include <stdint.h>

#define BB   64
#define SS   2048
#define EH   512
#define AH   512

#define SPLITS 64
#define SCH    (SS / SPLITS)    // 32

// scratch (no allocations allowed)
__device__ float g_dec_proj[BB * AH];
__device__ float g_score[BB * SS];
__device__ float g_ctx_part[SPLITS * BB * EH];

// ---------------------------------------------------------------------------
__device__ __forceinline__ uint32_t f2tf32(float x) {
    uint32_t r;
    asm("cvt.rna.tf32.f32 %0, %1;" : "=r"(r) : "f"(x));
    return r;
}
__device__ __forceinline__ float fast_tanh(float x) {
    float y; asm("tanh.approx.f32 %0, %1;" : "=f"(y) : "f"(x)); return y;
}
__device__ __forceinline__ void mma_tf32(float* c, const uint32_t* a, const uint32_t* b) {
    asm volatile(
        "mma.sync.aligned.m16n8k8.row.col.f32.tf32.tf32.f32 "
        "{%0,%1,%2,%3}, {%4,%5,%6,%7}, {%8,%9}, {%0,%1,%2,%3};\n"
        : "+f"(c[0]), "+f"(c[1]), "+f"(c[2]), "+f"(c[3])
        : "r"(a[0]), "r"(a[1]), "r"(a[2]), "r"(a[3]),
          "r"(b[0]), "r"(b[1]));
}

// ---------------------------------------------------------------------------
// K1: dec_proj[b,a] = sum_d dec_hidden[b,d] * W_dec[a,d]   grid (BB, 16)
// ---------------------------------------------------------------------------
__global__ void __launch_bounds__(128) dec_proj_kernel(
        const float* __restrict__ dec_hidden,
        const float* __restrict__ W_dec) {
    int b  = blockIdx.x;
    int ab = blockIdx.y * 32;
    __shared__ float sh[EH];
    for (int i = threadIdx.x; i < EH; i += 128)
        sh[i] = dec_hidden[b * EH + i];
    __syncthreads();

    int warp = threadIdx.x >> 5;
    int lane = threadIdx.x & 31;
    for (int a = warp; a < 32; a += 4) {
        const float* wr = W_dec + (size_t)(ab + a) * EH;
        float acc = 0.f;
        #pragma unroll 4
        for (int d = lane; d < EH; d += 32)
            acc += sh[d] * wr[d];
        #pragma unroll
        for (int o = 16; o > 0; o >>= 1)
            acc += __shfl_xor_sync(0xffffffffu, acc, o);
        if (lane == 0) g_dec_proj[b * AH + ab + a] = acc;
    }
}

// ---------------------------------------------------------------------------
// K2: fused score kernel (tf32 mma.sync m16n8k8), frag-major smem layout.
//     4-stage ring buffer, ONE barrier per TWO chunks, cross-pass pipelined.
//     (exact verified 580.0us configuration — DO NOT TOUCH)
//   score[b,s] = sum_a tanh(enc_proj[b,s,a] + dec_proj[b,a]) * v[a]
// ---------------------------------------------------------------------------
#define KT     32
#define NKCH   16          // chunks per a-pass; 64 global chunks
#define AW_PAD 1028
#define BW_PAD 1026
#define AWORDS (4 * AW_PAD)
#define BWORDS (4 * BW_PAD)
#define STWORDS (AWORDS + BWORDS)       // 8216 words per stage
#define OFF_ST0  0
#define OFF_ST1  (1 * STWORDS)
#define OFF_ST2  (2 * STWORDS)
#define OFF_ST3  (3 * STWORDS)
#define OFF_SV   (4 * STWORDS)
#define OFF_SDEC (OFF_SV + 128)
#define OFF_RED  (OFF_SDEC + 128)
#define SMEM_WORDS (OFF_RED + 512)
#define SMEM_BYTES (SMEM_WORDS * 4)     // 134528

// load regs for GLOBAL chunk gi (pass = gi>>4, k0 = (gi&15)*KT)
__device__ __forceinline__ void load_regs_g(float4* ra, float4* rb,
                                            const float* __restrict__ encb,
                                            const float* __restrict__ Wenc,
                                            int gi, int tid) {
    const int k0 = (gi & 15) * KT;
    const float* wbp = Wenc + (size_t)(gi >> 4) * 128 * EH;
    #pragma unroll
    for (int j = 0; j < 4; j++) {
        int i = tid + j * 256;
        int m = i >> 3, k4 = i & 7;
        ra[j] = *(const float4*)&encb[(size_t)m * EH + k0 + k4 * 4];
        rb[j] = *(const float4*)&wbp [(size_t)m * EH + k0 + k4 * 4];
    }
}

// stage pointer: A tile at stage base, B tile at stage base + AWORDS
__device__ __forceinline__ void store_tiles(uint32_t* __restrict__ St,
                                            const float4* ra, const float4* rb,
                                            int tid) {
    uint32_t* Ab = St;
    uint32_t* Bb = St + AWORDS;
    #pragma unroll
    for (int j = 0; j < 4; j++) {
        int i = tid + j * 256;
        int m = i >> 3, k4 = i & 7;
        int kb = k4 >> 1, khigh = k4 & 1;
        {
            int mb = m >> 4, gg = m & 7, rh = (m >> 3) & 1;
            int base = kb * AW_PAD + mb * 128 + khigh * 2 + rh;
            const float* f = &ra[j].x;
            #pragma unroll
            for (int c = 0; c < 4; c++)
                Ab[base + (gg * 4 + c) * 4] = f2tf32(f[c]);
        }
        {
            int nb = m >> 3, gg = m & 7;
            int base = kb * BW_PAD + nb * 64 + khigh;
            const float* f = &rb[j].x;
            #pragma unroll
            for (int c = 0; c < 4; c++)
                Bb[base + (gg * 4 + c) * 2] = f2tf32(f[c]);
        }
    }
}

__device__ __forceinline__ void mma_block(const uint32_t* __restrict__ St,
                                          float acc[4][4][4], int wid, int lane) {
    const uint32_t* As = St;
    const uint32_t* Bs = St + AWORDS;
    #pragma unroll
    for (int kb = 0; kb < 4; kb++) {
        uint4 af[4];
        #pragma unroll
        for (int mf = 0; mf < 4; mf++) {
            int mb = (wid & 1) * 4 + mf;
            af[mf] = *(const uint4*)&As[kb * AW_PAD + mb * 128 + lane * 4];
        }
        uint2 bf[4];
        #pragma unroll
        for (int nf = 0; nf < 4; nf++) {
            int nb = (wid >> 1) * 4 + nf;
            bf[nf] = *(const uint2*)&Bs[kb * BW_PAD + nb * 64 + lane * 2];
        }
        #pragma unroll
        for (int mf = 0; mf < 4; mf++)
            #pragma unroll
            for (int nf = 0; nf < 4; nf++)
                mma_tf32(acc[mf][nf], (const uint32_t*)&af[mf],
                         (const uint32_t*)&bf[nf]);
    }
}

__global__ void __launch_bounds__(256, 1) score_kernel(
        const float* __restrict__ enc,
        const float* __restrict__ Wenc,
        const float* __restrict__ v) {
    extern __shared__ uint32_t dsm[];
    const int b  = blockIdx.y;
    const int s0 = blockIdx.x * 128;
    const int tid = threadIdx.x;
    const int wid = tid >> 5;
    const int lane = tid & 31;
    const int g = lane >> 2;
    const int t = lane & 3;
    const int warp_m = (wid & 1) * 64;
    const int warp_n = (wid >> 1) * 32;
    const int wn_idx = wid >> 1;

    uint32_t* const T0 = dsm + OFF_ST0;
    uint32_t* const T1 = dsm + OFF_ST1;
    uint32_t* const T2 = dsm + OFF_ST2;
    uint32_t* const T3 = dsm + OFF_ST3;
    float* sv   = (float*)(dsm + OFF_SV);
    float* sdec = (float*)(dsm + OFF_SDEC);
    float* red  = (float*)(dsm + OFF_RED);

    const float* encb = enc + ((size_t)b * SS + s0) * EH;

    float srow = 0.f;

    // ---- prologue: chunks 0,1 -> T0,T1 ----
    float4 ra[4], rb[4];
    load_regs_g(ra, rb, encb, Wenc, 0, tid);
    store_tiles(T0, ra, rb, tid);
    load_regs_g(ra, rb, encb, Wenc, 1, tid);
    store_tiles(T1, ra, rb, tid);
    __syncthreads();

    for (int pass = 0; pass < 4; pass++) {
        const int a0 = pass * 128;

        if (tid < 128) {
            sv[tid]   = v[a0 + tid];
            sdec[tid] = g_dec_proj[b * AH + a0 + tid];
        }

        float acc[4][4][4];
        #pragma unroll
        for (int mf = 0; mf < 4; mf++)
            #pragma unroll
            for (int nf = 0; nf < 4; nf++)
                #pragma unroll
                for (int cc = 0; cc < 4; cc++) acc[mf][nf][cc] = 0.f;

        // ---- 4-chunk super-regions, one barrier per 2 chunks ----
        for (int ci = 0; ci < NKCH; ci += 4) {
            const int gi = pass * NKCH + ci;

            // region A: chunks gi (T0), gi+1 (T1); store gi+2->T2, gi+3->T3
            load_regs_g(ra, rb, encb, Wenc, gi + 2, tid);   // gi+2 <= 62
            mma_block(T0, acc, wid, lane);
            store_tiles(T2, ra, rb, tid);
            load_regs_g(ra, rb, encb, Wenc, gi + 3, tid);   // gi+3 <= 63
            mma_block(T1, acc, wid, lane);
            store_tiles(T3, ra, rb, tid);
            __syncthreads();

            // region B: chunks gi+2 (T2), gi+3 (T3); store gi+4->T0, gi+5->T1
            const bool p4 = (gi + 4 < 64);
            const bool p5 = (gi + 5 < 64);
            if (p4) load_regs_g(ra, rb, encb, Wenc, gi + 4, tid);
            mma_block(T2, acc, wid, lane);
            if (p4) store_tiles(T0, ra, rb, tid);
            if (p5) load_regs_g(ra, rb, encb, Wenc, gi + 5, tid);
            mma_block(T3, acc, wid, lane);
            if (p5) store_tiles(T1, ra, rb, tid);
            __syncthreads();
        }

        // ---- epilogue: tanh(acc + dec) * v, reduce over the 128 a-cols ----
        float rowsum[4][2];
        #pragma unroll
        for (int mf = 0; mf < 4; mf++) { rowsum[mf][0] = 0.f; rowsum[mf][1] = 0.f; }

        #pragma unroll
        for (int mf = 0; mf < 4; mf++) {
            #pragma unroll
            for (int nf = 0; nf < 4; nf++) {
                int nbase = warp_n + nf * 8 + t * 2;
                #pragma unroll
                for (int cc = 0; cc < 4; cc++) {
                    int n = nbase + (cc & 1);
                    float x = acc[mf][nf][cc] + sdec[n];
                    rowsum[mf][cc >> 1] += fast_tanh(x) * sv[n];
                }
            }
        }
        #pragma unroll
        for (int mf = 0; mf < 4; mf++) {
            #pragma unroll
            for (int o = 0; o < 2; o++) {
                rowsum[mf][o] += __shfl_xor_sync(0xffffffffu, rowsum[mf][o], 1);
                rowsum[mf][o] += __shfl_xor_sync(0xffffffffu, rowsum[mf][o], 2);
            }
        }
        if (t == 0) {
            #pragma unroll
            for (int mf = 0; mf < 4; mf++) {
                red[(warp_m + mf * 16 + g)     * 4 + wn_idx] = rowsum[mf][0];
                red[(warp_m + mf * 16 + g + 8) * 4 + wn_idx] = rowsum[mf][1];
            }
        }
        __syncthreads();
        if (tid < 128) {
            float4 rr = *(const float4*)&red[tid * 4];
            srow += (rr.x + rr.y) + (rr.z + rr.w);
        }
        __syncthreads();   // protects red + sv/sdec for next pass
    }

    if (tid < 128)
        g_score[b * SS + s0 + tid] = srow;
}

// ---------------------------------------------------------------------------
// K3 (fused): softmax (recomputed per block, deterministic) + partial context.
//     256 threads: softmax preamble over 8 scores/thread; context split-s —
//     group 0 handles s in [0,16), group 1 handles [16,32), smem combine.
// ---------------------------------------------------------------------------
__global__ void __launch_bounds__(256) context_partial_kernel(
        const float* __restrict__ enc,
        float* __restrict__ out_w) {
    const int b   = blockIdx.x;
    const int sp  = blockIdx.y;
    const int tid = threadIdx.x;
    const int lane = tid & 31;
    const int warp = tid >> 5;

    __shared__ float sredm[8];
    __shared__ float sreds[8];
    __shared__ float wsm[SCH];
    __shared__ float part[EH];

    const float* srow = g_score + b * SS;

    // 8 contiguous scores per thread
    float vals[8];
    float vmax = -1e30f;
    #pragma unroll
    for (int i = 0; i < 2; i++) {
        float4 v4 = *(const float4*)&srow[tid * 8 + i * 4];
        vals[i * 4 + 0] = v4.x; vals[i * 4 + 1] = v4.y;
        vals[i * 4 + 2] = v4.z; vals[i * 4 + 3] = v4.w;
    }
    #pragma unroll
    for (int i = 0; i < 8; i++) vmax = fmaxf(vmax, vals[i]);
    #pragma unroll
    for (int o = 16; o > 0; o >>= 1)
        vmax = fmaxf(vmax, __shfl_xor_sync(0xffffffffu, vmax, o));
    if (lane == 0) sredm[warp] = vmax;
    __syncthreads();
    float bmax = fmaxf(fmaxf(fmaxf(sredm[0], sredm[1]), fmaxf(sredm[2], sredm[3])),
                       fmaxf(fmaxf(sredm[4], sredm[5]), fmaxf(sredm[6], sredm[7])));

    float vsum = 0.f;
    #pragma unroll
    for (int i = 0; i < 8; i++) {
        vals[i] = expf(vals[i] - bmax);
        vsum += vals[i];
    }
    #pragma unroll
    for (int o = 16; o > 0; o >>= 1)
        vsum += __shfl_xor_sync(0xffffffffu, vsum, o);
    if (lane == 0) sreds[warp] = vsum;
    __syncthreads();
    float bsum = (((sreds[0] + sreds[1]) + (sreds[2] + sreds[3]))
                + ((sreds[4] + sreds[5]) + (sreds[6] + sreds[7])));
    float inv = __frcp_rn(bsum);

    if (sp == 0) {
        #pragma unroll
        for (int i = 0; i < 8; i++)
            out_w[b * SS + tid * 8 + i] = vals[i] * inv;
    }

    if (tid < SCH)
        wsm[tid] = expf(srow[sp * SCH + tid] - bmax) * inv;
    __syncthreads();

    // split-s partial context: grp 0 -> s [0,16), grp 1 -> s [16,32)
    const int grp = tid >> 7;
    const int el  = tid & 127;
    const int e4  = el << 2;
    const float* encb = enc
        + ((size_t)b * SS + (size_t)sp * SCH + grp * 16) * EH + e4;
    const float* wg = wsm + grp * 16;

    float4 acc = make_float4(0.f, 0.f, 0.f, 0.f);
    #pragma unroll 8
    for (int s = 0; s < 16; s++) {
        float ws = wg[s];
        float4 ev = *(const float4*)(encb + (size_t)s * EH);
        acc.x += ws * ev.x;
        acc.y += ws * ev.y;
        acc.z += ws * ev.z;
        acc.w += ws * ev.w;
    }
    if (grp == 1)
        *(float4*)&part[e4] = acc;
    __syncthreads();
    if (grp == 0) {
        float4 p = *(const float4*)&part[e4];
        acc.x += p.x; acc.y += p.y; acc.z += p.z; acc.w += p.w;
        *(float4*)&g_ctx_part[((size_t)sp * BB + b) * EH + e4] = acc;
    }
}

// ---------------------------------------------------------------------------
// K4: deterministic reduce, 4-way split-parallel (grid 512 x 256).
// ---------------------------------------------------------------------------
__global__ void __launch_bounds__(256) context_reduce_kernel(float* __restrict__ ctx) {
    __shared__ float part[4][64];
    const int t  = threadIdx.x >> 6;          // split-group 0..3
    const int el = threadIdx.x & 63;
    const int i  = blockIdx.x * 64 + el;      // element 0..BB*EH-1

    float s = 0.f;
    #pragma unroll
    for (int j = 0; j < 16; j++)
        s += g_ctx_part[(size_t)(t * 16 + j) * BB * EH + i];
    part[t][el] = s;
    __syncthreads();
    if (t == 0)
        ctx[i] = ((part[0][el] + part[1][el]) + (part[2][el] + part[3][el]));
}

// ---------------------------------------------------------------------------
extern "C" void kernel_launch(void* const* d_in, const int* in_sizes, int n_in,
                              void* d_out, int out_size) {
    const float* enc   = (const float*)d_in[0];  // [B,S,EH]
    const float* dec   = (const float*)d_in[1];  // [B,EH]
    const float* W_enc = (const float*)d_in[2];  // [AH,EH]
    const float* W_dec = (const float*)d_in[3];  // [AH,EH]
    const float* v     = (const float*)d_in[4];  // [1,AH]

    float* out = (float*)d_out;
    float* out_ctx = out;                 // [B, EH]
    float* out_w   = out + BB * EH;       // [B, S]

    static int smem_set = 0;
    if (!smem_set) {
        cudaFuncSetAttribute(score_kernel,
                             cudaFuncAttributeMaxDynamicSharedMemorySize,
                             SMEM_BYTES);
        smem_set = 1;
    }

    dim3 g1(BB, 16);
    dec_proj_kernel<<<g1, 128>>>(dec, W_dec);

    dim3 g2(SS / 128, BB);
    score_kernel<<<g2, 256, SMEM_BYTES>>>(enc, W_enc, v);

    dim3 g3(BB, SPLITS);
    context_partial_kernel<<<g3, 256>>>(enc, out_w);

    context_reduce_kernel<<<(BB * EH) / 64, 256>>>(out_ctx);
}